// round 3
// baseline (speedup 1.0000x reference)
#include <cuda_runtime.h>
#include <math.h>

#define NB    8
#define CI    64
#define CO    64
#define HH    160
#define WW    160
#define HW    25600      // 160*160
#define CHW   1638400    // 64*25600
#define NPIX  204800
#define KKT   9
#define OCF   27

typedef unsigned long long u64;

// ---------------- scratch (__device__ globals; no allocation allowed) ----------------
__device__ float g_py  [NB * KKT * HW];     // absolute sample y per (n,k,pixel)
__device__ float g_px  [NB * KKT * HW];     // absolute sample x
__device__ float g_m   [NB * KKT * HW];     // sigmoid mask
__device__ float g_woff[KKT * CI * 32];     // offset weights repacked [k][c][oc(pad32)]
__device__ float g_wmn [KKT * CI * CO];     // main   weights repacked [k][c][oc]

// ---------------- packed f32x2 helpers (b64 regs, "l" constraint) ----------------
__device__ __forceinline__ void fma2(u64& acc, u64 a, u64 b) {
    asm("fma.rn.f32x2 %0, %1, %2, %0;" : "+l"(acc) : "l"(a), "l"(b));
}
__device__ __forceinline__ u64 dup2(float a) {
    u64 r; asm("mov.b64 %0, {%1, %1};" : "=l"(r) : "f"(a)); return r;
}
__device__ __forceinline__ float lo32(u64 d) { return __int_as_float((unsigned)d); }
__device__ __forceinline__ float hi32(u64 d) { return __int_as_float((unsigned)(d >> 32)); }

// ---------------- kernel 0: weight repack ----------------
__global__ void repack_kernel(const float* __restrict__ offw,
                              const float* __restrict__ wmain) {
    int i = blockIdx.x * 256 + threadIdx.x;
    if (i < KKT * CI * CO) {                 // 36864
        int k = i / (CI * CO);
        int r = i % (CI * CO);
        int c = r / CO;
        int o = r % CO;
        g_wmn[i] = wmain[o * CI * KKT + c * KKT + k];
    }
    if (i < KKT * CI * 32) {                 // 18432
        int k = i / (CI * 32);
        int r = i % (CI * 32);
        int c = r / 32;
        int o = r % 32;
        g_woff[i] = (o < OCF) ? offw[o * CI * KKT + c * KKT + k] : 0.f;
    }
}

// ---------------- kernel A: offset conv (27ch) + transform -> g_py/g_px/g_m ----------
// tile: 256 pixels x 32 oc ; 256 threads ; thread tile 4px x 8oc (oc-paired f32x2)
__global__ __launch_bounds__(256) void offset_kernel(const float* __restrict__ fea,
                                                     const float* __restrict__ flows,
                                                     const float* __restrict__ offb) {
    extern __shared__ float sm[];
    float* As = sm;              // [64][256] = 16384 floats
    float* Bs = sm + 16384;      // [64][32]  = 2048 floats

    const int t  = threadIdx.x;
    const int p0 = blockIdx.x * 256;
    const int n  = p0 / HW;
    const int s0 = p0 % HW;
    const int s  = s0 + t;
    const int y  = s / WW;
    const int x  = s % WW;

    const int px0 = 4 * (t & 63);
    const int oc0 = 8 * (t >> 6);

    u64 acc[16];
    #pragma unroll
    for (int q = 0; q < 16; q++) acc[q] = 0ULL;

    #pragma unroll 1
    for (int k = 0; k < 9; k++) {
        const int ky = k / 3 - 1, kx = k % 3 - 1;
        __syncthreads();
        // B fill (repacked, coalesced)
        {
            const float4* src = (const float4*)(g_woff + k * 2048);
            float4* dst = (float4*)Bs;
            dst[t]       = src[t];
            dst[t + 256] = src[t + 256];
        }
        // A fill: thread t owns pixel column t, loops channels
        {
            const int ry = y + ky, rx = x + kx;
            const bool ok = ((unsigned)ry < (unsigned)HH) && ((unsigned)rx < (unsigned)WW);
            const float* fp = fea + n * CHW + ry * WW + rx;
            #pragma unroll
            for (int c = 0; c < 64; c++)
                As[c * 256 + t] = ok ? __ldg(fp + c * HW) : 0.f;
        }
        __syncthreads();
        // mainloop
        #pragma unroll 8
        for (int kk = 0; kk < 64; kk++) {
            float4     a   = *(const float4*)(As + kk * 256 + px0);
            ulonglong2 b01 = *(const ulonglong2*)(Bs + kk * 32 + oc0);
            ulonglong2 b23 = *(const ulonglong2*)(Bs + kk * 32 + oc0 + 4);
            u64 a0 = dup2(a.x), a1 = dup2(a.y), a2 = dup2(a.z), a3 = dup2(a.w);
            fma2(acc[0],  a0, b01.x); fma2(acc[1],  a0, b01.y); fma2(acc[2],  a0, b23.x); fma2(acc[3],  a0, b23.y);
            fma2(acc[4],  a1, b01.x); fma2(acc[5],  a1, b01.y); fma2(acc[6],  a1, b23.x); fma2(acc[7],  a1, b23.y);
            fma2(acc[8],  a2, b01.x); fma2(acc[9],  a2, b01.y); fma2(acc[10], a2, b23.x); fma2(acc[11], a2, b23.y);
            fma2(acc[12], a3, b01.x); fma2(acc[13], a3, b01.y); fma2(acc[14], a3, b23.x); fma2(acc[15], a3, b23.y);
        }
    }

    // stage results to shared: Cs[32 oc][256 px] (reuses As region)
    __syncthreads();
    float* Cs = sm;
    #pragma unroll
    for (int j = 0; j < 4; j++) {
        float4 vlo = make_float4(lo32(acc[0*4+j]), lo32(acc[1*4+j]), lo32(acc[2*4+j]), lo32(acc[3*4+j]));
        float4 vhi = make_float4(hi32(acc[0*4+j]), hi32(acc[1*4+j]), hi32(acc[2*4+j]), hi32(acc[3*4+j]));
        *(float4*)(Cs + (oc0 + 2*j)     * 256 + px0) = vlo;
        *(float4*)(Cs + (oc0 + 2*j + 1) * 256 + px0) = vhi;
    }
    __syncthreads();

    // per-pixel transform (thread t -> pixel t)
    const float fx_ = __ldg(flows + n * 2 * HW + s);        // flows[n,0] -> added to dx
    const float fy_ = __ldg(flows + n * 2 * HW + HW + s);   // flows[n,1] -> added to dy
    const int base = n * KKT * HW + s;
    #pragma unroll
    for (int k = 0; k < 9; k++) {
        float dy = tanhf(Cs[(2*k)   * 256 + t] + __ldg(offb + 2*k))     * 10.f + fy_;
        float dx = tanhf(Cs[(2*k+1) * 256 + t] + __ldg(offb + 2*k + 1)) * 10.f + fx_;
        float mm = Cs[(18+k) * 256 + t] + __ldg(offb + 18 + k);
        mm = 1.f / (1.f + expf(-mm));
        g_py[base + k * HW] = (float)(y - 1 + k / 3) + dy;
        g_px[base + k * HW] = (float)(x - 1 + k % 3) + dx;
        g_m [base + k * HW] = mm;
    }
}

// ---------------- kernel B: deformable gather + GEMM ----------------
// tile: 128 pixels x 64 oc ; 256 threads ; thread tile 4px x 8oc (oc-paired f32x2)
__global__ __launch_bounds__(256) void dcn_kernel(const float* __restrict__ input,
                                                  const float* __restrict__ bias,
                                                  float* __restrict__ out) {
    extern __shared__ float sm[];
    float* As = sm;              // [64][128] = 8192 floats
    float* Bs = sm + 8192;       // [64][64]  = 4096 floats

    const int t   = threadIdx.x;
    const int p0  = blockIdx.x * 128;
    const int n   = p0 / HW;
    const int s0  = p0 % HW;
    const int pxl = t & 127;          // gather column
    const int hi  = t >> 7;           // channel parity for gather
    const int s   = s0 + pxl;

    const int px0 = 4 * (t & 31);
    const int oc0 = 8 * (t >> 5);

    u64 acc[16];
    #pragma unroll
    for (int q = 0; q < 16; q++) acc[q] = 0ULL;

    #pragma unroll 1
    for (int k = 0; k < 9; k++) {
        __syncthreads();
        // B fill
        {
            const float4* src = (const float4*)(g_wmn + k * 4096);
            float4* dst = (float4*)Bs;
            #pragma unroll
            for (int i = 0; i < 4; i++) dst[t + i * 256] = src[t + i * 256];
        }
        // bilinear params for this thread's pixel + tap
        {
            const int sidx = (n * KKT + k) * HW + s;
            const float py = g_py[sidx];
            const float px = g_px[sidx];
            const float m  = g_m[sidx];
            const float y0f = floorf(py), x0f = floorf(px);
            const float fy = py - y0f,  fx = px - x0f;
            const int y0 = (int)y0f, x0 = (int)x0f;
            float w00 = (1.f - fy) * (1.f - fx) * m;
            float w01 = (1.f - fy) * fx * m;
            float w10 = fy * (1.f - fx) * m;
            float w11 = fy * fx * m;
            const bool vy0 = (unsigned)y0       < (unsigned)HH;
            const bool vy1 = (unsigned)(y0 + 1) < (unsigned)HH;
            const bool vx0 = (unsigned)x0       < (unsigned)WW;
            const bool vx1 = (unsigned)(x0 + 1) < (unsigned)WW;
            w00 = (vy0 && vx0) ? w00 : 0.f;
            w01 = (vy0 && vx1) ? w01 : 0.f;
            w10 = (vy1 && vx0) ? w10 : 0.f;
            w11 = (vy1 && vx1) ? w11 : 0.f;
            const int yc0 = min(max(y0, 0), HH - 1), yc1 = min(max(y0 + 1, 0), HH - 1);
            const int xc0 = min(max(x0, 0), WW - 1), xc1 = min(max(x0 + 1, 0), WW - 1);
            const int o00 = yc0 * WW + xc0, o01 = yc0 * WW + xc1;
            const int o10 = yc1 * WW + xc0, o11 = yc1 * WW + xc1;
            const float* ip = input + n * CHW + hi * HW;
            #pragma unroll 8
            for (int i = 0; i < 32; i++) {
                const float* p = ip + 2 * i * HW;
                float v = w00 * __ldg(p + o00) + w01 * __ldg(p + o01)
                        + w10 * __ldg(p + o10) + w11 * __ldg(p + o11);
                As[(2 * i + hi) * 128 + pxl] = v;
            }
        }
        __syncthreads();
        // mainloop
        #pragma unroll 8
        for (int kk = 0; kk < 64; kk++) {
            float4     a   = *(const float4*)(As + kk * 128 + px0);
            ulonglong2 b01 = *(const ulonglong2*)(Bs + kk * 64 + oc0);
            ulonglong2 b23 = *(const ulonglong2*)(Bs + kk * 64 + oc0 + 4);
            u64 a0 = dup2(a.x), a1 = dup2(a.y), a2 = dup2(a.z), a3 = dup2(a.w);
            fma2(acc[0],  a0, b01.x); fma2(acc[1],  a0, b01.y); fma2(acc[2],  a0, b23.x); fma2(acc[3],  a0, b23.y);
            fma2(acc[4],  a1, b01.x); fma2(acc[5],  a1, b01.y); fma2(acc[6],  a1, b23.x); fma2(acc[7],  a1, b23.y);
            fma2(acc[8],  a2, b01.x); fma2(acc[9],  a2, b01.y); fma2(acc[10], a2, b23.x); fma2(acc[11], a2, b23.y);
            fma2(acc[12], a3, b01.x); fma2(acc[13], a3, b01.y); fma2(acc[14], a3, b23.x); fma2(acc[15], a3, b23.y);
        }
    }

    // epilogue: vectorized float4 stores over the 4 consecutive pixels
    float* outp = out + n * CHW + s0 + px0;
    #pragma unroll
    for (int j = 0; j < 4; j++) {
        const int oce = oc0 + 2 * j;
        const float b0 = __ldg(bias + oce);
        const float b1 = __ldg(bias + oce + 1);
        float4 vlo = make_float4(lo32(acc[0*4+j]) + b0, lo32(acc[1*4+j]) + b0,
                                 lo32(acc[2*4+j]) + b0, lo32(acc[3*4+j]) + b0);
        float4 vhi = make_float4(hi32(acc[0*4+j]) + b1, hi32(acc[1*4+j]) + b1,
                                 hi32(acc[2*4+j]) + b1, hi32(acc[3*4+j]) + b1);
        *(float4*)(outp + (oce)     * HW) = vlo;
        *(float4*)(outp + (oce + 1) * HW) = vhi;
    }
}

// ---------------- launch ----------------
extern "C" void kernel_launch(void* const* d_in, const int* in_sizes, int n_in,
                              void* d_out, int out_size) {
    (void)in_sizes; (void)n_in; (void)out_size;
    const float* input  = (const float*)d_in[0];
    const float* fea    = (const float*)d_in[1];
    const float* flows  = (const float*)d_in[2];
    const float* offw   = (const float*)d_in[3];
    const float* offb   = (const float*)d_in[4];
    const float* weight = (const float*)d_in[5];
    const float* bias   = (const float*)d_in[6];
    float* out = (float*)d_out;

    cudaFuncSetAttribute(offset_kernel, cudaFuncAttributeMaxDynamicSharedMemorySize, 73728);
    cudaFuncSetAttribute(dcn_kernel,    cudaFuncAttributeMaxDynamicSharedMemorySize, 49152);

    repack_kernel<<<144, 256>>>(offw, weight);
    offset_kernel<<<NPIX / 256, 256, 73728>>>(fea, flows, offb);
    dcn_kernel<<<NPIX / 128, 256, 49152>>>(input, bias, out);
}